// round 1
// baseline (speedup 1.0000x reference)
#include <cuda_runtime.h>
#include <cuda_bf16.h>
#include <math_constants.h>

#define Bb  2
#define Ls  4096
#define Ds  512
#define Hh  8
#define HDs 64
#define FFs 2048
#define WIN 128

// ---------------- scratch (device globals: allocation-guard safe) ----------
__device__ float g_q  [Bb*Ls*Ds];
__device__ float g_k  [Bb*Ls*Ds];
__device__ float g_v  [Bb*Ls*Ds];
__device__ float g_att[Bb*Ls*Ds];
__device__ float g_prj[Bb*Ls*Ds];
__device__ float g_h  [Bb*Ls*Ds];
__device__ float g_ff1[Bb*Ls*FFs];
__device__ float g_ff2[Bb*Ls*Ds];

// ---------------- tiled fp32 SGEMM: C[M,N] = A[M,K] @ W[K,N] + bias --------
#define BM 128
#define BN 64
#define BK 16
#define TM 8
#define TN 4

__global__ __launch_bounds__(256)
void sgemm_bias(const float* __restrict__ A, const float* __restrict__ W,
                const float* __restrict__ bias, float* __restrict__ C,
                int M, int N, int K, int relu)
{
    __shared__ float As[BK][BM + 4];
    __shared__ float Bs[BK][BN];

    const int tid = threadIdx.x;
    const int bm  = blockIdx.y * BM;
    const int bn  = blockIdx.x * BN;
    const int tr  = tid >> 4;          // 0..15
    const int tc  = tid & 15;          // 0..15

    const int arow = tid >> 2;         // 0..63
    const int acol = (tid & 3) * 4;    // 0,4,8,12
    const int brow = tid >> 4;         // 0..15
    const int bcol = (tid & 15) * 4;   // 0..60

    float acc[TM][TN];
#pragma unroll
    for (int i = 0; i < TM; i++)
#pragma unroll
        for (int j = 0; j < TN; j++) acc[i][j] = 0.f;

    for (int k0 = 0; k0 < K; k0 += BK) {
        float4 a0 = *(const float4*)&A[(size_t)(bm + arow)      * K + k0 + acol];
        float4 a1 = *(const float4*)&A[(size_t)(bm + arow + 64) * K + k0 + acol];
        As[acol + 0][arow] = a0.x;  As[acol + 1][arow] = a0.y;
        As[acol + 2][arow] = a0.z;  As[acol + 3][arow] = a0.w;
        As[acol + 0][arow + 64] = a1.x;  As[acol + 1][arow + 64] = a1.y;
        As[acol + 2][arow + 64] = a1.z;  As[acol + 3][arow + 64] = a1.w;

        float4 b0 = *(const float4*)&W[(size_t)(k0 + brow) * N + bn + bcol];
        *(float4*)&Bs[brow][bcol] = b0;

        __syncthreads();
#pragma unroll
        for (int kk = 0; kk < BK; kk++) {
            float a[TM], b[TN];
#pragma unroll
            for (int i = 0; i < TM; i++) a[i] = As[kk][tr * TM + i];
#pragma unroll
            for (int j = 0; j < TN; j++) b[j] = Bs[kk][tc * TN + j];
#pragma unroll
            for (int i = 0; i < TM; i++)
#pragma unroll
                for (int j = 0; j < TN; j++)
                    acc[i][j] = fmaf(a[i], b[j], acc[i][j]);
        }
        __syncthreads();
    }

    const int cn = bn + tc * TN;
    float4 bv = *(const float4*)&bias[cn];
#pragma unroll
    for (int i = 0; i < TM; i++) {
        float4 r;
        r.x = acc[i][0] + bv.x;
        r.y = acc[i][1] + bv.y;
        r.z = acc[i][2] + bv.z;
        r.w = acc[i][3] + bv.w;
        if (relu) {
            r.x = fmaxf(r.x, 0.f); r.y = fmaxf(r.y, 0.f);
            r.z = fmaxf(r.z, 0.f); r.w = fmaxf(r.w, 0.f);
        }
        *(float4*)&C[(size_t)(bm + tr * TM + i) * N + cn] = r;
    }
}

// ---------------- banded attention (flash-style, one thread per query) -----
__global__ __launch_bounds__(128)
void attn_banded(const float* __restrict__ q, const float* __restrict__ k,
                 const float* __restrict__ v, float* __restrict__ out)
{
    const int bh = blockIdx.y;
    const int b  = bh >> 3;
    const int h  = bh & 7;
    const int q0 = blockIdx.x * 128;
    const int tid = threadIdx.x;
    const int qi  = q0 + tid;

    const float* qrow = q + ((size_t)(b * Ls + qi) * Ds + h * HDs);
    float4 qv[16];
#pragma unroll
    for (int i = 0; i < 16; i++) qv[i] = ((const float4*)qrow)[i];

    float4 acc[16];
#pragma unroll
    for (int i = 0; i < 16; i++) acc[i] = make_float4(0.f, 0.f, 0.f, 0.f);
    float m = -CUDART_INF_F, l = 0.f;

    __shared__ float4 Ks[64][16];
    __shared__ float4 Vs[64][16];

    const int kstart = max(0, q0 - WIN);
    const int kend   = min(Ls, q0 + 128 + WIN);  // exclusive

    for (int kt = kstart; kt < kend; kt += 64) {
        __syncthreads();
        for (int i = tid; i < 1024; i += 128) {
            int r = i >> 4, c = i & 15;
            const float* kr = k + ((size_t)(b * Ls + kt + r) * Ds + h * HDs);
            const float* vr = v + ((size_t)(b * Ls + kt + r) * Ds + h * HDs);
            Ks[r][c] = ((const float4*)kr)[c];
            Vs[r][c] = ((const float4*)vr)[c];
        }
        __syncthreads();

        int lo = max(qi - WIN, kt) - kt;
        int hi = min(qi + WIN + 1, kt + 64) - kt;
        for (int kk = lo; kk < hi; kk++) {
            float s = 0.f;
#pragma unroll
            for (int i = 0; i < 16; i++) {
                float4 kv = Ks[kk][i];
                s = fmaf(qv[i].x, kv.x, s);
                s = fmaf(qv[i].y, kv.y, s);
                s = fmaf(qv[i].z, kv.z, s);
                s = fmaf(qv[i].w, kv.w, s);
            }
            s *= 0.125f;  // 1/sqrt(64)
            if (s <= m) {
                float p = __expf(s - m);
                l += p;
#pragma unroll
                for (int i = 0; i < 16; i++) {
                    float4 vv = Vs[kk][i];
                    acc[i].x = fmaf(p, vv.x, acc[i].x);
                    acc[i].y = fmaf(p, vv.y, acc[i].y);
                    acc[i].z = fmaf(p, vv.z, acc[i].z);
                    acc[i].w = fmaf(p, vv.w, acc[i].w);
                }
            } else {
                float cs = __expf(m - s);
                m = s;
                l = fmaf(l, cs, 1.f);
#pragma unroll
                for (int i = 0; i < 16; i++) {
                    float4 vv = Vs[kk][i];
                    acc[i].x = fmaf(acc[i].x, cs, vv.x);
                    acc[i].y = fmaf(acc[i].y, cs, vv.y);
                    acc[i].z = fmaf(acc[i].z, cs, vv.z);
                    acc[i].w = fmaf(acc[i].w, cs, vv.w);
                }
            }
        }
    }

    float inv = 1.f / l;
    float* orow = out + ((size_t)(b * Ls + qi) * Ds + h * HDs);
#pragma unroll
    for (int i = 0; i < 16; i++) {
        float4 r = acc[i];
        r.x *= inv; r.y *= inv; r.z *= inv; r.w *= inv;
        ((float4*)orow)[i] = r;
    }
}

// ---------------- residual + LayerNorm -------------------------------------
__global__ __launch_bounds__(128)
void add_ln(const float* __restrict__ x, const float* __restrict__ r,
            const float* __restrict__ g, const float* __restrict__ bta,
            float* __restrict__ out)
{
    const int row = blockIdx.x;
    const int tid = threadIdx.x;
    const float* xr = x + (size_t)row * Ds;
    const float* rr = r + (size_t)row * Ds;

    __shared__ float t[Ds];
    __shared__ float s1[4], s2[4];

    float s = 0.f, ss = 0.f;
#pragma unroll
    for (int i = 0; i < 4; i++) {
        int c = tid + i * 128;
        float u = xr[c] + rr[c];
        t[c] = u;
        s += u;
        ss = fmaf(u, u, ss);
    }
#pragma unroll
    for (int o = 16; o; o >>= 1) {
        s  += __shfl_xor_sync(0xffffffffu, s,  o);
        ss += __shfl_xor_sync(0xffffffffu, ss, o);
    }
    if ((tid & 31) == 0) { s1[tid >> 5] = s; s2[tid >> 5] = ss; }
    __syncthreads();
    float S  = s1[0] + s1[1] + s1[2] + s1[3];
    float SS = s2[0] + s2[1] + s2[2] + s2[3];
    float mu   = S * (1.f / Ds);
    float var  = SS * (1.f / Ds) - mu * mu;
    float rstd = rsqrtf(var + 1e-5f);
#pragma unroll
    for (int i = 0; i < 4; i++) {
        int c = tid + i * 128;
        out[(size_t)row * Ds + c] = (t[c] - mu) * rstd * g[c] + bta[c];
    }
}

// ---------------- launch ----------------------------------------------------
extern "C" void kernel_launch(void* const* d_in, const int* in_sizes, int n_in,
                              void* d_out, int out_size)
{
    const float* x    = (const float*)d_in[0];
    const float* Wq   = (const float*)d_in[1];
    const float* bq   = (const float*)d_in[2];
    const float* Wk   = (const float*)d_in[3];
    const float* bk   = (const float*)d_in[4];
    const float* Wv   = (const float*)d_in[5];
    const float* bv   = (const float*)d_in[6];
    const float* Wo   = (const float*)d_in[7];
    const float* bo   = (const float*)d_in[8];
    const float* ln1g = (const float*)d_in[9];
    const float* ln1b = (const float*)d_in[10];
    const float* W1   = (const float*)d_in[11];
    const float* b1   = (const float*)d_in[12];
    const float* W2   = (const float*)d_in[13];
    const float* b2   = (const float*)d_in[14];
    const float* ln2g = (const float*)d_in[15];
    const float* ln2b = (const float*)d_in[16];
    float* out = (float*)d_out;

    float *q, *k, *v, *att, *prj, *h, *ff1, *ff2;
    cudaGetSymbolAddress((void**)&q,   g_q);
    cudaGetSymbolAddress((void**)&k,   g_k);
    cudaGetSymbolAddress((void**)&v,   g_v);
    cudaGetSymbolAddress((void**)&att, g_att);
    cudaGetSymbolAddress((void**)&prj, g_prj);
    cudaGetSymbolAddress((void**)&h,   g_h);
    cudaGetSymbolAddress((void**)&ff1, g_ff1);
    cudaGetSymbolAddress((void**)&ff2, g_ff2);

    const int M = Bb * Ls;

    dim3 gD(Ds / BN, M / BM);    // N=512  GEMMs
    dim3 gF(FFs / BN, M / BM);   // N=2048 GEMM

    sgemm_bias<<<gD, 256>>>(x, Wq, bq, q, M, Ds, Ds, 0);
    sgemm_bias<<<gD, 256>>>(x, Wk, bk, k, M, Ds, Ds, 0);
    sgemm_bias<<<gD, 256>>>(x, Wv, bv, v, M, Ds, Ds, 0);

    attn_banded<<<dim3(Ls / 128, Bb * Hh), 128>>>(q, k, v, att);

    sgemm_bias<<<gD, 256>>>(att, Wo, bo, prj, M, Ds, Ds, 0);
    add_ln<<<M, 128>>>(x, prj, ln1g, ln1b, h);

    sgemm_bias<<<gF, 256>>>(h, W1, b1, ff1, M, FFs, Ds, 1);
    sgemm_bias<<<gD, 256>>>(ff1, W2, b2, ff2, M, Ds, FFs, 0);
    add_ln<<<M, 128>>>(h, ff2, ln2g, ln2b, out);
}

// round 2
// speedup vs baseline: 2.6015x; 2.6015x over previous
#include <cuda_runtime.h>
#include <cuda_bf16.h>
#include <math_constants.h>
#include <cstdint>

#define Bb  2
#define Ls  4096
#define Ds  512
#define Hh  8
#define HDs 64
#define FFs 2048
#define WIN 128

// ---------------- scratch (device globals: allocation-guard safe) ----------
__device__ float g_q  [Bb*Ls*Ds];
__device__ float g_k  [Bb*Ls*Ds];
__device__ float g_v  [Bb*Ls*Ds];
__device__ float g_att[Bb*Ls*Ds];
__device__ float g_prj[Bb*Ls*Ds];
__device__ float g_h  [Bb*Ls*Ds];
__device__ float g_ff1[Bb*Ls*FFs];
__device__ float g_ff2[Bb*Ls*Ds];

// ======================= tf32 tensor-core GEMM ==============================
// C[M,N] = A[M,K] @ W[K,N] + bias, optional relu.
// 128 threads, block tile 128x64, warp tile 64x32 (2x2 warps),
// mma.m16n8k8 tf32, fp32 accumulate.
#define GBM 128
#define GBN 64
#define GBK 32

__device__ __forceinline__ uint32_t f2tf(float x) {
    uint32_t u;
    asm("cvt.rna.tf32.f32 %0, %1;" : "=r"(u) : "f"(x));
    return u;
}

__global__ __launch_bounds__(128)
void tgemm_bias(const float* __restrict__ A, const float* __restrict__ W,
                const float* __restrict__ bias, float* __restrict__ C,
                int M, int N, int K, int relu)
{
    __shared__ uint32_t As[GBM][GBK + 4];   // [m][k], pad 4 -> stride 36 (16B aligned, conflict-free)
    __shared__ uint32_t Bs[GBK][GBN + 8];   // [k][n], pad 8 -> stride 72 (16B aligned, conflict-free)

    const int tid  = threadIdx.x;
    const int lane = tid & 31;
    const int warp = tid >> 5;            // 0..3
    const int gid  = lane >> 2;           // 0..7
    const int tg   = lane & 3;            // 0..3
    const int wm   = (warp >> 1) * 64;    // warp row offset
    const int wn   = (warp & 1) * 32;     // warp col offset
    const int bm   = blockIdx.y * GBM;
    const int bn   = blockIdx.x * GBN;

    float d[4][4][4];
#pragma unroll
    for (int i = 0; i < 4; i++)
#pragma unroll
        for (int j = 0; j < 4; j++)
#pragma unroll
            for (int c = 0; c < 4; c++) d[i][j][c] = 0.f;

    for (int k0 = 0; k0 < K; k0 += GBK) {
        // load A tile 128x32 (coalesced: warp covers 4 rows x 128B)
#pragma unroll
        for (int it = 0; it < 8; it++) {
            int idx = tid + it * 128;
            int r = idx >> 3, c4 = (idx & 7) * 4;
            float4 v = *(const float4*)&A[(size_t)(bm + r) * K + k0 + c4];
            uint4 u = make_uint4(f2tf(v.x), f2tf(v.y), f2tf(v.z), f2tf(v.w));
            *(uint4*)&As[r][c4] = u;
        }
        // load B tile 32x64
#pragma unroll
        for (int it = 0; it < 4; it++) {
            int idx = tid + it * 128;
            int r = idx >> 4, c4 = (idx & 15) * 4;
            float4 v = *(const float4*)&W[(size_t)(k0 + r) * N + bn + c4];
            uint4 u = make_uint4(f2tf(v.x), f2tf(v.y), f2tf(v.z), f2tf(v.w));
            *(uint4*)&Bs[r][c4] = u;
        }
        __syncthreads();

#pragma unroll
        for (int kk = 0; kk < GBK; kk += 8) {
            uint32_t bf[4][2];
#pragma unroll
            for (int jn = 0; jn < 4; jn++) {
                bf[jn][0] = Bs[kk + tg    ][wn + jn * 8 + gid];
                bf[jn][1] = Bs[kk + tg + 4][wn + jn * 8 + gid];
            }
#pragma unroll
            for (int im = 0; im < 4; im++) {
                const int mr = wm + im * 16 + gid;
                uint32_t a0 = As[mr    ][kk + tg    ];
                uint32_t a1 = As[mr + 8][kk + tg    ];
                uint32_t a2 = As[mr    ][kk + tg + 4];
                uint32_t a3 = As[mr + 8][kk + tg + 4];
#pragma unroll
                for (int jn = 0; jn < 4; jn++) {
                    asm volatile(
                        "mma.sync.aligned.m16n8k8.row.col.f32.tf32.tf32.f32 "
                        "{%0,%1,%2,%3}, {%4,%5,%6,%7}, {%8,%9}, {%0,%1,%2,%3};\n"
                        : "+f"(d[im][jn][0]), "+f"(d[im][jn][1]),
                          "+f"(d[im][jn][2]), "+f"(d[im][jn][3])
                        : "r"(a0), "r"(a1), "r"(a2), "r"(a3),
                          "r"(bf[jn][0]), "r"(bf[jn][1]));
                }
            }
        }
        __syncthreads();
    }

    // epilogue: c0,c1 -> (row, col..col+1); c2,c3 -> (row+8, col..col+1)
#pragma unroll
    for (int jn = 0; jn < 4; jn++) {
        const int col = bn + wn + jn * 8 + 2 * tg;
        float2 bv = *(const float2*)&bias[col];
#pragma unroll
        for (int im = 0; im < 4; im++) {
            const int row = bm + wm + im * 16 + gid;
            float2 r0, r1;
            r0.x = d[im][jn][0] + bv.x;  r0.y = d[im][jn][1] + bv.y;
            r1.x = d[im][jn][2] + bv.x;  r1.y = d[im][jn][3] + bv.y;
            if (relu) {
                r0.x = fmaxf(r0.x, 0.f); r0.y = fmaxf(r0.y, 0.f);
                r1.x = fmaxf(r1.x, 0.f); r1.y = fmaxf(r1.y, 0.f);
            }
            *(float2*)&C[(size_t)row       * N + col] = r0;
            *(float2*)&C[(size_t)(row + 8) * N + col] = r1;
        }
    }
}

// ================= banded attention (flash-style, batched keys) =============
__global__ __launch_bounds__(128)
void attn_banded(const float* __restrict__ q, const float* __restrict__ k,
                 const float* __restrict__ v, float* __restrict__ out)
{
    const int bh = blockIdx.y;
    const int b  = bh >> 3;
    const int h  = bh & 7;
    const int q0 = blockIdx.x * 128;
    const int tid = threadIdx.x;
    const int qi  = q0 + tid;

    const float* qrow = q + ((size_t)(b * Ls + qi) * Ds + h * HDs);
    float4 qv[16];
#pragma unroll
    for (int i = 0; i < 16; i++) qv[i] = ((const float4*)qrow)[i];

    float4 acc[16];
#pragma unroll
    for (int i = 0; i < 16; i++) acc[i] = make_float4(0.f, 0.f, 0.f, 0.f);
    float m = -1e30f, l = 0.f;

    __shared__ float4 Ks[64][16];
    __shared__ float4 Vs[64][16];

    const int kstart = max(0, q0 - WIN);
    const int kend   = min(Ls, q0 + 128 + WIN);  // exclusive; range is multiple of 64

    for (int kt = kstart; kt < kend; kt += 64) {
        __syncthreads();
        for (int i = tid; i < 1024; i += 128) {
            int r = i >> 4, c = i & 15;
            const float* kr = k + ((size_t)(b * Ls + kt + r) * Ds + h * HDs);
            const float* vr = v + ((size_t)(b * Ls + kt + r) * Ds + h * HDs);
            Ks[r][c] = ((const float4*)kr)[c];
            Vs[r][c] = ((const float4*)vr)[c];
        }
        __syncthreads();

        const int lo = max(qi - WIN, kt) - kt;          // first valid key in tile
        const int hi = min(qi + WIN + 1, kt + 64) - kt; // exclusive

#pragma unroll 1
        for (int kk0 = 0; kk0 < 64; kk0 += 8) {
            if (kk0 + 8 <= lo || kk0 >= hi) continue;

            // 8 independent dot-product chains (ILP=8)
            float s[8];
#pragma unroll
            for (int j = 0; j < 8; j++) s[j] = 0.f;
#pragma unroll
            for (int i = 0; i < 16; i++) {
                const float4 qq = qv[i];
#pragma unroll
                for (int j = 0; j < 8; j++) {
                    float4 kv = Ks[kk0 + j][i];
                    float t = s[j];
                    t = fmaf(qq.x, kv.x, t);
                    t = fmaf(qq.y, kv.y, t);
                    t = fmaf(qq.z, kv.z, t);
                    t = fmaf(qq.w, kv.w, t);
                    s[j] = t;
                }
            }
            bool valid[8];
#pragma unroll
            for (int j = 0; j < 8; j++) {
                valid[j] = (kk0 + j >= lo) && (kk0 + j < hi);
                s[j] = valid[j] ? s[j] * 0.125f : -1e30f;
            }
            float bm = s[0];
#pragma unroll
            for (int j = 1; j < 8; j++) bm = fmaxf(bm, s[j]);

            if (bm > m) {
                float cs = __expf(m - bm);
                m = bm;
                l *= cs;
#pragma unroll
                for (int i = 0; i < 16; i++) {
                    acc[i].x *= cs; acc[i].y *= cs;
                    acc[i].z *= cs; acc[i].w *= cs;
                }
            }
            float psum = 0.f;
#pragma unroll
            for (int j = 0; j < 8; j++) {
                s[j] = valid[j] ? __expf(s[j] - m) : 0.f;  // reuse s as p
                psum += s[j];
            }
            l += psum;
#pragma unroll
            for (int i = 0; i < 16; i++) {
                float4 a = acc[i];
#pragma unroll
                for (int j = 0; j < 8; j++) {
                    float4 vv = Vs[kk0 + j][i];
                    a.x = fmaf(s[j], vv.x, a.x);
                    a.y = fmaf(s[j], vv.y, a.y);
                    a.z = fmaf(s[j], vv.z, a.z);
                    a.w = fmaf(s[j], vv.w, a.w);
                }
                acc[i] = a;
            }
        }
    }

    const float inv = 1.f / l;
    float* orow = out + ((size_t)(b * Ls + qi) * Ds + h * HDs);
#pragma unroll
    for (int i = 0; i < 16; i++) {
        float4 r = acc[i];
        r.x *= inv; r.y *= inv; r.z *= inv; r.w *= inv;
        ((float4*)orow)[i] = r;
    }
}

// ---------------- residual + LayerNorm -------------------------------------
__global__ __launch_bounds__(128)
void add_ln(const float* __restrict__ x, const float* __restrict__ r,
            const float* __restrict__ g, const float* __restrict__ bta,
            float* __restrict__ out)
{
    const int row = blockIdx.x;
    const int tid = threadIdx.x;
    const float* xr = x + (size_t)row * Ds;
    const float* rr = r + (size_t)row * Ds;

    __shared__ float t[Ds];
    __shared__ float s1[4], s2[4];

    float s = 0.f, ss = 0.f;
#pragma unroll
    for (int i = 0; i < 4; i++) {
        int c = tid + i * 128;
        float u = xr[c] + rr[c];
        t[c] = u;
        s += u;
        ss = fmaf(u, u, ss);
    }
#pragma unroll
    for (int o = 16; o; o >>= 1) {
        s  += __shfl_xor_sync(0xffffffffu, s,  o);
        ss += __shfl_xor_sync(0xffffffffu, ss, o);
    }
    if ((tid & 31) == 0) { s1[tid >> 5] = s; s2[tid >> 5] = ss; }
    __syncthreads();
    float S  = s1[0] + s1[1] + s1[2] + s1[3];
    float SS = s2[0] + s2[1] + s2[2] + s2[3];
    float mu   = S * (1.f / Ds);
    float var  = SS * (1.f / Ds) - mu * mu;
    float rstd = rsqrtf(var + 1e-5f);
#pragma unroll
    for (int i = 0; i < 4; i++) {
        int c = tid + i * 128;
        out[(size_t)row * Ds + c] = (t[c] - mu) * rstd * g[c] + bta[c];
    }
}

// ---------------- launch ----------------------------------------------------
extern "C" void kernel_launch(void* const* d_in, const int* in_sizes, int n_in,
                              void* d_out, int out_size)
{
    const float* x    = (const float*)d_in[0];
    const float* Wq   = (const float*)d_in[1];
    const float* bq   = (const float*)d_in[2];
    const float* Wk   = (const float*)d_in[3];
    const float* bk   = (const float*)d_in[4];
    const float* Wv   = (const float*)d_in[5];
    const float* bv   = (const float*)d_in[6];
    const float* Wo   = (const float*)d_in[7];
    const float* bo   = (const float*)d_in[8];
    const float* ln1g = (const float*)d_in[9];
    const float* ln1b = (const float*)d_in[10];
    const float* W1   = (const float*)d_in[11];
    const float* b1   = (const float*)d_in[12];
    const float* W2   = (const float*)d_in[13];
    const float* b2   = (const float*)d_in[14];
    const float* ln2g = (const float*)d_in[15];
    const float* ln2b = (const float*)d_in[16];
    float* out = (float*)d_out;

    float *q, *k, *v, *att, *prj, *h, *ff1, *ff2;
    cudaGetSymbolAddress((void**)&q,   g_q);
    cudaGetSymbolAddress((void**)&k,   g_k);
    cudaGetSymbolAddress((void**)&v,   g_v);
    cudaGetSymbolAddress((void**)&att, g_att);
    cudaGetSymbolAddress((void**)&prj, g_prj);
    cudaGetSymbolAddress((void**)&h,   g_h);
    cudaGetSymbolAddress((void**)&ff1, g_ff1);
    cudaGetSymbolAddress((void**)&ff2, g_ff2);

    const int M = Bb * Ls;

    dim3 gD(Ds / GBN, M / GBM);    // N=512  GEMMs
    dim3 gF(FFs / GBN, M / GBM);   // N=2048 GEMM

    tgemm_bias<<<gD, 128>>>(x, Wq, bq, q, M, Ds, Ds, 0);
    tgemm_bias<<<gD, 128>>>(x, Wk, bk, k, M, Ds, Ds, 0);
    tgemm_bias<<<gD, 128>>>(x, Wv, bv, v, M, Ds, Ds, 0);

    attn_banded<<<dim3(Ls / 128, Bb * Hh), 128>>>(q, k, v, att);

    tgemm_bias<<<gD, 128>>>(att, Wo, bo, prj, M, Ds, Ds, 0);
    add_ln<<<M, 128>>>(x, prj, ln1g, ln1b, h);

    tgemm_bias<<<gF, 128>>>(h, W1, b1, ff1, M, FFs, Ds, 1);
    tgemm_bias<<<gD, 128>>>(ff1, W2, b2, ff2, M, Ds, FFs, 0);
    add_ln<<<M, 128>>>(h, ff2, ln2g, ln2b, out);
}